// round 17
// baseline (speedup 1.0000x reference)
#include <cuda_runtime.h>
#include <math.h>
#include <stdint.h>

#define TT   1024
#define HH   512
#define SZ   (64 * HH)
#define NCTA 128
#define NTHR 512

// SMEM (bytes): A 64x132 fp32 | RED | W0 8x1028 words | WN 64x516 words
#define A_ST 0
#define RED  33792
#define W0P  58368
#define WNP  91264
#define SMEM_BYTES 223360

typedef unsigned long long ull;

__device__ __align__(16) float g_state[5 * SZ];  // 0:s0 1:s1 2:s2 3:s3 4:s5
__device__ __align__(16) float g_h[SZ];
__device__ ull g_bar = 0ULL;

__device__ __forceinline__ void grid_bar() {
    __syncthreads();
    if (threadIdx.x == 0) {
        __threadfence();
        ull my = atomicAdd(&g_bar, 1ULL);
        ull tgt = (my / (ull)NCTA + 1ULL) * (ull)NCTA;
        while (*((volatile ull*)&g_bar) < tgt) __nanosleep(64);
        __threadfence();
    }
    __syncthreads();
}

__device__ __forceinline__ float sigm(float x) { return 1.0f / (1.0f + expf(-x)); }

__device__ __forceinline__ uint32_t bf16r(float v) {      // round-to-nearest bf16, as fp32-hi bits
    uint32_t u = __float_as_uint(v);
    return (u + 0x7FFFu + ((u >> 16) & 1u)) & 0xFFFF0000u;
}
__device__ __forceinline__ uint32_t tf32r(float x) {
    uint32_t r; asm("cvt.rna.tf32.f32 %0,%1;" : "=r"(r) : "f"(x)); return r;
}
__device__ __forceinline__ void mmat(float* d, const uint32_t* a, uint32_t b0, uint32_t b1) {
    asm volatile("mma.sync.aligned.m16n8k8.row.col.f32.tf32.tf32.f32 "
                 "{%0,%1,%2,%3},{%4,%5,%6,%7},{%8,%9},{%0,%1,%2,%3};"
                 : "+f"(d[0]), "+f"(d[1]), "+f"(d[2]), "+f"(d[3])
                 : "r"(a[0]), "r"(a[1]), "r"(a[2]), "r"(a[3]), "r"(b0), "r"(b1));
}

// One level GEMM: D[64 rows x 8 cols] per mat, K = NCHUNK*128.
// Chunk c source: c < SPLITC ? srcA + c*128 : srcB + (c-SPLITC)*128 (row stride 512).
// Warp (m = warp&3, kg = warp>>2); kg owns k8-tiles kg*4..kg*4+3 of each chunk.
// 3xTF32: A split on the fly; W words = (bf16hi<<16 | bf16lo).
template <int NMAT, int NCHUNK, int SPLITC>
__device__ __forceinline__ void run_gemm(char* __restrict__ smc,
                                         const float* __restrict__ srcA,
                                         const float* __restrict__ srcB,
                                         const int* mats, int rbase) {
    const int tid = threadIdx.x, warp = tid >> 5, lane = tid & 31;
    const int m = warp & 3, kg = warp >> 2, g = lane >> 2, tg = lane & 3;
    const int sr = tid >> 3, cp = tid & 7;
    float* A = (float*)(smc + A_ST);

    float D[NMAT][4];
#pragma unroll
    for (int q = 0; q < NMAT; q++)
#pragma unroll
        for (int i = 0; i < 4; i++) D[q][i] = 0.f;

    float pf[16];
    {
        const float* p = srcA + sr * 512 + cp * 16;
#pragma unroll
        for (int i = 0; i < 4; i++) *(float4*)(pf + i * 4) = *(const float4*)(p + i * 4);
    }

    for (int c = 0; c < NCHUNK; c++) {
        float* arow = A + sr * 132 + cp * 16;
#pragma unroll
        for (int i = 0; i < 4; i++) *(float4*)(arow + i * 4) = *(float4*)(pf + i * 4);
        __syncthreads();
        if (c + 1 < NCHUNK) {
            const float* base = (c + 1 < SPLITC) ? srcA + (c + 1) * 128
                                                 : srcB + (c + 1 - SPLITC) * 128;
            const float* p = base + sr * 512 + cp * 16;
#pragma unroll
            for (int i = 0; i < 4; i++) *(float4*)(pf + i * 4) = *(const float4*)(p + i * 4);
        }
#pragma unroll
        for (int e = 0; e < 4; e++) {
            const int kt = kg * 4 + e;
            const int kl = kt * 8 + tg;              // k within chunk (+tg)
            float a0 = A[(m * 16 + g) * 132 + kl];
            float a1 = A[(m * 16 + g + 8) * 132 + kl];
            float a2 = A[(m * 16 + g) * 132 + kl + 4];
            float a3 = A[(m * 16 + g + 8) * 132 + kl + 4];
            uint32_t ah[4], al[4];
            ah[0] = tf32r(a0); al[0] = tf32r(a0 - __uint_as_float(ah[0]));
            ah[1] = tf32r(a1); al[1] = tf32r(a1 - __uint_as_float(ah[1]));
            ah[2] = tf32r(a2); al[2] = tf32r(a2 - __uint_as_float(ah[2]));
            ah[3] = tf32r(a3); al[3] = tf32r(a3 - __uint_as_float(ah[3]));
            const int kgl = c * 128 + kl;
#pragma unroll
            for (int q = 0; q < NMAT; q++) {
                const uint32_t* w = (mats[q] < 0)
                    ? (const uint32_t*)(smc + W0P) + g * 1028
                    : (const uint32_t*)(smc + WNP) + mats[q] * 4128 + g * 516;
                uint32_t w0 = w[kgl], w1 = w[kgl + 4];
                uint32_t bh0 = w0 & 0xFFFF0000u, bl0 = w0 << 16;
                uint32_t bh1 = w1 & 0xFFFF0000u, bl1 = w1 << 16;
                mmat(D[q], ah, bh0, bh1);
                mmat(D[q], ah, bl0, bl1);
                mmat(D[q], al, bh0, bh1);
            }
        }
        __syncthreads();
    }
#pragma unroll
    for (int q = 0; q < NMAT; q++)
        *(float4*)(smc + RED + (((rbase + q) * 4 + kg) * 4 + m) * 512 + lane * 16) =
            make_float4(D[q][0], D[q][1], D[q][2], D[q][3]);
    __syncthreads();
}

__device__ __forceinline__ float4 redsum(const char* smc, int q, int m, int lane) {
    float4 a = *(const float4*)(smc + RED + ((q * 4 + 0) * 4 + m) * 512 + lane * 16);
#pragma unroll
    for (int k = 1; k < 4; k++) {
        float4 b = *(const float4*)(smc + RED + ((q * 4 + k) * 4 + m) * 512 + lane * 16);
        a.x += b.x; a.y += b.y; a.z += b.z; a.w += b.w;
    }
    return a;
}

__global__ void __launch_bounds__(NTHR, 1)
darts_kernel(const float* __restrict__ x,
             const float* __restrict__ W0,
             const float* __restrict__ Ws,
             float* __restrict__ out) {
    extern __shared__ char smc[];
    const int tid = threadIdx.x, warp = tid >> 5, lane = tid & 31;
    const int Jb = blockIdx.x * 4;

    // Weights once: col n -> J = Jb + (n>>1) + (n&1)*512 (even n: c-col, odd: h-col)
    for (int p = tid; p < 8192; p += NTHR) {             // W0: 8 cols x 1024 k
        int n = p & 7, k = p >> 3;
        float v = W0[(size_t)k * 1024 + Jb + (n >> 1) + (n & 1) * HH];
        uint32_t hi = bf16r(v);
        uint32_t lo = bf16r(v - __uint_as_float(hi));
        ((uint32_t*)(smc + W0P))[n * 1028 + k] = hi | (lo >> 16);
    }
    for (int p = tid; p < 32768; p += NTHR) {            // WN: 8 mats x 8 cols x 512 k
        int i = p >> 12, n = p & 7, k = (p >> 3) & 511;
        float v = Ws[(size_t)i * HH * 1024 + (size_t)k * 1024 + Jb + (n >> 1) + (n & 1) * HH];
        uint32_t hi = bf16r(v);
        uint32_t lo = bf16r(v - __uint_as_float(hi));
        ((uint32_t*)(smc + WNP))[i * 4128 + n * 516 + k] = hi | (lo >> 16);
    }

    // Owners: warps 0-3 (m = warp). Lane: rows R0 = m*16 + (lane>>2), R1 = R0+8; col J = Jb + (lane&3).
    const bool own = (warp < 4);
    const int R0 = warp * 16 + (lane >> 2), R1 = R0 + 8;
    const int J = Jb + (lane & 3);
    const int i0 = R0 * HH + J, i1 = R1 * HH + J;
    if (own) { g_h[i0] = 0.f; g_h[i1] = 0.f; }

    float hp0 = 0.f, hp1 = 0.f;
    float S0a, S0b, S1a, S1b, S2a, S2b, S3a, S3b, S5a, S5b, SUa, SUb;
    S0a = S0b = S1a = S1b = S2a = S2b = S3a = S3b = S5a = S5b = SUa = SUb = 0.f;

    const int mW0[1] = {-1}, m0[1] = {0}, m123[3] = {1, 2, 3};
    const int m4[1] = {4}, m6[1] = {6}, m57[2] = {5, 7};

    grid_bar();

    for (int t = 0; t < TT; t++) {
        // LVL0: s0 = highway([x | h_prev] @ W0), K=1024
        run_gemm<1, 8, 4>(smc, x + (size_t)t * SZ, g_h, mW0, 0);
        if (own) {
            float4 v = redsum(smc, 0, warp, lane);
            S0a = hp0 + sigm(v.x) * (tanhf(v.y) - hp0);
            S0b = hp1 + sigm(v.z) * (tanhf(v.w) - hp1);
            g_state[i0] = S0a; g_state[i1] = S0b;
        }
        grid_bar();

        // LVL1: node0 (pred s0, sigmoid)
        run_gemm<1, 4, 4>(smc, g_state, g_state, m0, 0);
        if (own) {
            float4 v = redsum(smc, 0, warp, lane);
            S1a = S0a + sigm(v.x) * (sigm(v.y) - S0a);
            S1b = S0b + sigm(v.z) * (sigm(v.w) - S0b);
            g_state[SZ + i0] = S1a; g_state[SZ + i1] = S1b;
            SUa = S1a; SUb = S1b;
        }
        grid_bar();

        // LVL2: nodes 1(relu), 2(relu), 3(identity), pred s1
        run_gemm<3, 4, 4>(smc, g_state + SZ, g_state, m123, 0);
        if (own) {
            float4 a = redsum(smc, 0, warp, lane);
            float4 b = redsum(smc, 1, warp, lane);
            float4 cc = redsum(smc, 2, warp, lane);
            S2a = S1a + sigm(a.x) * (fmaxf(a.y, 0.f) - S1a);
            S2b = S1b + sigm(a.z) * (fmaxf(a.w, 0.f) - S1b);
            S3a = S1a + sigm(b.x) * (fmaxf(b.y, 0.f) - S1a);
            S3b = S1b + sigm(b.z) * (fmaxf(b.w, 0.f) - S1b);
            float s4a = S1a + sigm(cc.x) * (cc.y - S1a);
            float s4b = S1b + sigm(cc.z) * (cc.w - S1b);
            g_state[2 * SZ + i0] = S2a; g_state[2 * SZ + i1] = S2b;
            g_state[3 * SZ + i0] = S3a; g_state[3 * SZ + i1] = S3b;
            SUa += S2a + S3a + s4a; SUb += S2b + S3b + s4b;
        }
        grid_bar();

        // LVL3: node4 (pred s2, tanh); node6 (pred s3, tanh)
        run_gemm<1, 4, 4>(smc, g_state + 2 * SZ, g_state, m4, 0);
        run_gemm<1, 4, 4>(smc, g_state + 3 * SZ, g_state, m6, 1);
        if (own) {
            float4 a = redsum(smc, 0, warp, lane);
            float4 b = redsum(smc, 1, warp, lane);
            S5a = S2a + sigm(a.x) * (tanhf(a.y) - S2a);
            S5b = S2b + sigm(a.z) * (tanhf(a.w) - S2b);
            float s7a = S3a + sigm(b.x) * (tanhf(b.y) - S3a);
            float s7b = S3b + sigm(b.z) * (tanhf(b.w) - S3b);
            g_state[4 * SZ + i0] = S5a; g_state[4 * SZ + i1] = S5b;
            SUa += S5a + s7a; SUb += S5b + s7b;
        }
        grid_bar();

        // LVL4: node5 (sigmoid); node7 (relu), pred s5
        run_gemm<2, 4, 4>(smc, g_state + 4 * SZ, g_state, m57, 0);
        if (own) {
            float4 a = redsum(smc, 0, warp, lane);
            float4 b = redsum(smc, 1, warp, lane);
            float s6a = S5a + sigm(a.x) * (sigm(a.y) - S5a);
            float s6b = S5b + sigm(a.z) * (sigm(a.w) - S5b);
            float s8a = S5a + sigm(b.x) * (fmaxf(b.y, 0.f) - S5a);
            float s8b = S5b + sigm(b.z) * (fmaxf(b.w, 0.f) - S5b);
            SUa += s6a + s8a; SUb += s6b + s8b;
            float hn0 = SUa * 0.125f, hn1 = SUb * 0.125f;
            out[(size_t)t * SZ + i0] = hn0;
            out[(size_t)t * SZ + i1] = hn1;
            g_h[i0] = hn0; g_h[i1] = hn1;
            hp0 = hn0; hp1 = hn1;
            if (t == TT - 1) {                       // hiddens[-1][None]
                out[(size_t)TT * SZ + i0] = hn0;
                out[(size_t)TT * SZ + i1] = hn1;
            }
        }
        grid_bar();
    }
}

extern "C" void kernel_launch(void* const* d_in, const int* in_sizes, int n_in,
                              void* d_out, int out_size) {
    const float* x  = (const float*)d_in[0];
    const float* W0 = (const float*)d_in[1];
    const float* Ws = (const float*)d_in[2];
    float* out = (float*)d_out;
    cudaFuncSetAttribute(darts_kernel,
                         cudaFuncAttributeMaxDynamicSharedMemorySize, SMEM_BYTES);
    darts_kernel<<<NCTA, NTHR, SMEM_BYTES>>>(x, W0, Ws, out);
}